// round 1
// baseline (speedup 1.0000x reference)
#include <cuda_runtime.h>

#define B_TOT 8192
#define T_STEPS 256
#define SD 12          // state dim
#define AD 4           // action dim
#define DD 16          // D = SD + AD
#define HH 16          // hidden
#define GG 64          // 4*H

#define BPB 8          // batches per block
#define THREADS (BPB * 16)
#define NBLOCKS (B_TOT / BPB)

// Preprocessed weights (device globals: no allocation allowed)
__device__ float4 g_WxT[DD * HH];  // [d][j] -> (row j, j+16, j+32, j+48) of folded x->gates matrix
__device__ float4 g_WhT[HH * HH];  // [k][j] -> rows of W_hh
__device__ float4 g_S[HH];         // rowsums (for LN mean correction)
__device__ float4 g_Bc[HH];        // combined bias
__device__ float  g_Wo[SD * HH];   // W_out row-major
__device__ float  g_bo[SD];

__global__ void vm_prep(const float* __restrict__ ln_gamma,
                        const float* __restrict__ ln_beta,
                        const float* __restrict__ W_in,   // [H][D]
                        const float* __restrict__ b_in,   // [H]
                        const float* __restrict__ W_ih,   // [G][H]
                        const float* __restrict__ W_hh,   // [G][H]
                        const float* __restrict__ b_ih,
                        const float* __restrict__ b_hh,
                        const float* __restrict__ W_out,  // [SD][H]
                        const float* __restrict__ b_out)
{
    int r = threadIdx.x;   // gate row 0..63
    if (r < GG) {
        int j  = r & 15;
        int gi = r >> 4;
        // Wc[r][d] = sum_k W_ih[r][k] * W_in[k][d]   (fold W_in into W_ih)
        float S = 0.f, bB = 0.f;
        for (int d = 0; d < DD; d++) {
            float acc = 0.f;
            for (int k = 0; k < HH; k++) acc += W_ih[r * HH + k] * W_in[k * DD + d];
            float wp = acc * ln_gamma[d];          // fold gamma
            bB += acc * ln_beta[d];                // fold beta
            S += wp;
            ((float*)g_WxT)[(d * HH + j) * 4 + gi] = wp;
        }
        float bi = 0.f;
        for (int k = 0; k < HH; k++) bi += W_ih[r * HH + k] * b_in[k];
        ((float*)g_S)[j * 4 + gi]  = S;
        ((float*)g_Bc)[j * 4 + gi] = bB + bi + b_ih[r] + b_hh[r];
        for (int k = 0; k < HH; k++)
            ((float*)g_WhT)[(k * HH + j) * 4 + gi] = W_hh[r * HH + k];
    }
    if (r < SD) {
        for (int k = 0; k < HH; k++) g_Wo[r * HH + k] = W_out[r * HH + k];
        g_bo[r] = b_out[r];
    }
}

__device__ __forceinline__ float sigm(float x) {
    float e = __expf(-x);
    return __fdividef(1.f, 1.f + e);
}
__device__ __forceinline__ float tanh_f(float x) {
    float ax = fabsf(x);
    float e = __expf(-2.f * ax);
    float t = __fdividef(1.f - e, 1.f + e);
    return copysignf(t, x);
}

__global__ __launch_bounds__(THREADS) void vm_main(
    const float* __restrict__ init_state,   // [B][1][SD]
    const float* __restrict__ commands,     // [B][T][AD]
    float* __restrict__ out)                // [B][T][SD]
{
    __shared__ float4 sWx[DD * HH];
    __shared__ float4 sWh[HH * HH];
    __shared__ float4 sS[HH], sB[HH];
    __shared__ __align__(16) float sWo[SD * HH];
    __shared__ float sbo[SD];
    __shared__ __align__(16) float xbuf[BPB][16];
    __shared__ __align__(16) float hbuf[BPB][16];

    int tid = threadIdx.x;
    for (int i = tid; i < DD * HH; i += THREADS) sWx[i] = g_WxT[i];
    for (int i = tid; i < HH * HH; i += THREADS) sWh[i] = g_WhT[i];
    if (tid < HH) { sS[tid] = g_S[tid]; sB[tid] = g_Bc[tid]; }
    for (int i = tid; i < SD * HH; i += THREADS) sWo[i] = g_Wo[i];
    if (tid < SD) sbo[tid] = g_bo[tid];

    int lb = tid >> 4;      // local batch within block
    int j  = tid & 15;      // hidden-unit / state-slot index
    int b  = blockIdx.x * BPB + lb;

    float st = (j < SD) ? init_state[b * SD + j] : 0.f;
    float h = 0.f, c = 0.f;
    hbuf[lb][j] = 0.f;
    __syncthreads();

    const float* cmdp = commands + b * (T_STEPS * AD);
    float* outp = out + (size_t)b * (T_STEPS * SD);

    // sincos partner lane (pairs (1,2),(3,4),(5,6))
    int p = ((j >= 1) && (j <= 6)) ? (j + ((j & 1) ? 1 : -1)) : j;

    for (int t = 0; t < T_STEPS; t++) {
        float xv = st;
        if (j >= SD) xv = cmdp[t * AD + (j - SD)];
        xbuf[lb][j] = xv;
        __syncwarp();

        float xr[DD], hr[HH];
        #pragma unroll
        for (int q = 0; q < 4; q++) {
            float4 v = ((const float4*)xbuf[lb])[q];
            xr[q*4+0] = v.x; xr[q*4+1] = v.y; xr[q*4+2] = v.z; xr[q*4+3] = v.w;
            float4 w = ((const float4*)hbuf[lb])[q];
            hr[q*4+0] = w.x; hr[q*4+1] = w.y; hr[q*4+2] = w.z; hr[q*4+3] = w.w;
        }

        // LN stats over x (16 elems)
        float s0 = 0.f, s1 = 0.f, q0 = 0.f, q1 = 0.f;
        #pragma unroll
        for (int d = 0; d < DD; d += 2) {
            s0 += xr[d];     q0 = fmaf(xr[d],   xr[d],   q0);
            s1 += xr[d+1];   q1 = fmaf(xr[d+1], xr[d+1], q1);
        }
        float mu   = (s0 + s1) * 0.0625f;
        float var  = fmaf(-mu, mu, (q0 + q1) * 0.0625f);
        float rstd = rsqrtf(var + 1e-5f);

        // fused gate dots: ax = W'_rows . x_raw, ah = W_hh_rows . h
        float4 ax = {0.f,0.f,0.f,0.f}, ah = {0.f,0.f,0.f,0.f};
        #pragma unroll
        for (int d = 0; d < DD; d++) {
            float4 w = sWx[d * HH + j];
            ax.x = fmaf(w.x, xr[d], ax.x);
            ax.y = fmaf(w.y, xr[d], ax.y);
            ax.z = fmaf(w.z, xr[d], ax.z);
            ax.w = fmaf(w.w, xr[d], ax.w);
            float4 u = sWh[d * HH + j];
            ah.x = fmaf(u.x, hr[d], ah.x);
            ah.y = fmaf(u.y, hr[d], ah.y);
            ah.z = fmaf(u.z, hr[d], ah.z);
            ah.w = fmaf(u.w, hr[d], ah.w);
        }
        float4 Sv = sS[j], Bv = sB[j];
        float gi = fmaf(rstd, fmaf(-mu, Sv.x, ax.x), Bv.x) + ah.x;
        float gf = fmaf(rstd, fmaf(-mu, Sv.y, ax.y), Bv.y) + ah.y;
        float gg = fmaf(rstd, fmaf(-mu, Sv.z, ax.z), Bv.z) + ah.z;
        float go = fmaf(rstd, fmaf(-mu, Sv.w, ax.w), Bv.w) + ah.w;

        float ig = sigm(gi), fg = sigm(gf), og = sigm(go);
        float gt = tanh_f(gg);
        c = fmaf(fg, c, ig * gt);
        h = og * tanh_f(c);

        __syncwarp();
        hbuf[lb][j] = h;
        __syncwarp();

        // state += h @ W_out.T + b_out  (lanes 0..11)
        if (j < SD) {
            const float4* wr = (const float4*)(sWo + j * HH);
            const float4* hh = (const float4*)hbuf[lb];
            float a0 = 0.f, a1 = 0.f, a2 = 0.f, a3 = 0.f;
            #pragma unroll
            for (int q2 = 0; q2 < 4; q2++) {
                float4 w = wr[q2];
                float4 hv = hh[q2];
                a0 = fmaf(w.x, hv.x, a0);
                a1 = fmaf(w.y, hv.y, a1);
                a2 = fmaf(w.z, hv.z, a2);
                a3 = fmaf(w.w, hv.w, a3);
            }
            st += (a0 + a1) + (a2 + a3) + sbo[j];
        }

        // sincos normalization via intra-half-warp shuffle
        float other = __shfl_sync(0xffffffffu, st, p, 16);
        if ((j >= 1) && (j <= 6)) {
            float nrm = __fsqrt_rn(fmaf(st, st, other * other)) + 1e-8f;
            st = __fdividef(st, nrm);
        }

        if (j < SD) outp[t * SD + j] = st;
    }
}

extern "C" void kernel_launch(void* const* d_in, const int* in_sizes, int n_in,
                              void* d_out, int out_size) {
    const float* init_state = (const float*)d_in[0];
    const float* commands   = (const float*)d_in[1];
    const float* ln_gamma   = (const float*)d_in[2];
    const float* ln_beta    = (const float*)d_in[3];
    const float* W_in       = (const float*)d_in[4];
    const float* b_in       = (const float*)d_in[5];
    const float* W_ih       = (const float*)d_in[6];
    const float* W_hh       = (const float*)d_in[7];
    const float* b_ih       = (const float*)d_in[8];
    const float* b_hh       = (const float*)d_in[9];
    const float* W_out      = (const float*)d_in[10];
    const float* b_out      = (const float*)d_in[11];
    float* out = (float*)d_out;

    vm_prep<<<1, 64>>>(ln_gamma, ln_beta, W_in, b_in, W_ih, W_hh, b_ih, b_hh, W_out, b_out);
    vm_main<<<NBLOCKS, THREADS>>>(init_state, commands, out);
}

// round 7
// speedup vs baseline: 1.0963x; 1.0963x over previous
#include <cuda_runtime.h>

#define B_TOT 8192
#define T_STEPS 256
#define SD 12          // state dim
#define AD 4           // action dim
#define DD 16          // D = SD + AD
#define HH 16          // hidden
#define GG 64          // 4*H

#define BPB 4          // batches per block
#define THREADS (BPB * 16)
#define NBLOCKS (B_TOT / BPB)

typedef unsigned long long ull;

// Preprocessed packed weights (device globals)
// g_WxP[j*32 + p*4 + c] : float2 = (Wc'[c*16+j][2p], Wc'[c*16+j][2p+1])  (gamma folded)
// g_WhP same for W_hh
__device__ float2 g_WxP[HH * 32];
__device__ float2 g_WhP[HH * 32];
__device__ float4 g_S[HH];         // rowsums of folded Wx (LN mean correction)
__device__ float4 g_Bc[HH];        // combined bias
__device__ float2 g_WoP[SD * 8];   // W_out packed pairs
__device__ float  g_bo[SD];

__global__ void vm_prep(const float* __restrict__ ln_gamma,
                        const float* __restrict__ ln_beta,
                        const float* __restrict__ W_in,   // [H][D]
                        const float* __restrict__ b_in,   // [H]
                        const float* __restrict__ W_ih,   // [G][H]
                        const float* __restrict__ W_hh,   // [G][H]
                        const float* __restrict__ b_ih,
                        const float* __restrict__ b_hh,
                        const float* __restrict__ W_out,  // [SD][H]
                        const float* __restrict__ b_out)
{
    int r = threadIdx.x;   // gate row 0..63
    if (r < GG) {
        int j  = r & 15;
        int gi = r >> 4;
        float wp[DD];
        float S = 0.f, bB = 0.f;
        for (int d = 0; d < DD; d++) {
            float acc = 0.f;
            for (int k = 0; k < HH; k++) acc += W_ih[r * HH + k] * W_in[k * DD + d];
            wp[d] = acc * ln_gamma[d];             // fold gamma
            bB += acc * ln_beta[d];                // fold beta
            S += wp[d];
        }
        float bi = 0.f;
        for (int k = 0; k < HH; k++) bi += W_ih[r * HH + k] * b_in[k];
        ((float*)g_S)[j * 4 + gi]  = S;
        ((float*)g_Bc)[j * 4 + gi] = bB + bi + b_ih[r] + b_hh[r];
        for (int p = 0; p < 8; p++) {
            g_WxP[j * 32 + p * 4 + gi] = make_float2(wp[2 * p], wp[2 * p + 1]);
            g_WhP[j * 32 + p * 4 + gi] = make_float2(W_hh[r * HH + 2 * p],
                                                     W_hh[r * HH + 2 * p + 1]);
        }
    }
    if (r < SD) {
        for (int p = 0; p < 8; p++)
            g_WoP[r * 8 + p] = make_float2(W_out[r * HH + 2 * p], W_out[r * HH + 2 * p + 1]);
        g_bo[r] = b_out[r];
    }
}

__device__ __forceinline__ void fma2(ull& acc, ull w, ull x) {
    asm("fma.rn.f32x2 %0, %1, %2, %0;" : "+l"(acc) : "l"(w), "l"(x));
}
__device__ __forceinline__ void add2(ull& acc, ull x) {
    asm("add.rn.f32x2 %0, %0, %1;" : "+l"(acc) : "l"(x));
}
__device__ __forceinline__ ull mul2(ull a, ull b) {
    ull r; asm("mul.rn.f32x2 %0, %1, %2;" : "=l"(r) : "l"(a), "l"(b)); return r;
}
__device__ __forceinline__ float2 up(ull v) {
    float2 r; asm("mov.b64 {%0, %1}, %2;" : "=f"(r.x), "=f"(r.y) : "l"(v)); return r;
}

__device__ __forceinline__ float sigm(float x) {
    float e = __expf(-x);
    return __fdividef(1.f, 1.f + e);
}
__device__ __forceinline__ float tanh_f(float x) {
    float ax = fabsf(x);
    float e = __expf(-2.f * ax);
    float t = __fdividef(1.f - e, 1.f + e);
    return copysignf(t, x);
}

__global__ __launch_bounds__(THREADS) void vm_main(
    const float* __restrict__ init_state,   // [B][1][SD]
    const float* __restrict__ commands,     // [B][T][AD]
    float* __restrict__ out)                // [B][T][SD]
{
    __shared__ __align__(16) float xbuf[BPB][16];
    __shared__ __align__(16) float hbuf[BPB][16];

    int tid = threadIdx.x;
    int lb = tid >> 4;      // local batch within block
    int j  = tid & 15;      // hidden-unit / state-slot index
    int b  = blockIdx.x * BPB + lb;

    // hoist packed weights into registers (loop-invariant)
    ull Wx[32], Wh[32];
    const ull* wxp = (const ull*)g_WxP + j * 32;
    const ull* whp = (const ull*)g_WhP + j * 32;
    #pragma unroll
    for (int i = 0; i < 32; i++) { Wx[i] = wxp[i]; Wh[i] = whp[i]; }

    ull Wo[8];
    float bo = 0.f;
    {
        int jo = (j < SD) ? j : 0;
        const ull* wop = (const ull*)g_WoP + jo * 8;
        #pragma unroll
        for (int i = 0; i < 8; i++) Wo[i] = wop[i];
        if (j < SD) bo = g_bo[j];
    }
    float4 Sv = g_S[j];
    float4 Bv = g_Bc[j];

    float st = (j < SD) ? init_state[b * SD + j] : 0.f;
    float h = 0.f, c = 0.f;
    hbuf[lb][j] = 0.f;
    xbuf[lb][j] = st;   // x for t=0 state part; cmd part overwritten below

    const float* cmdp = commands + b * (T_STEPS * AD);
    float* outp = out + (size_t)b * (T_STEPS * SD);

    // sincos partner lane (pairs (1,2),(3,4),(5,6))
    int p = ((j >= 1) && (j <= 6)) ? (j + ((j & 1) ? 1 : -1)) : j;

    __syncwarp();

    for (int t = 0; t < T_STEPS; t++) {
        if (j >= SD) xbuf[lb][j] = cmdp[t * AD + (j - SD)];
        __syncwarp();

        ull xp[8], hp[8];
        const ull* xq = (const ull*)xbuf[lb];
        const ull* hq = (const ull*)hbuf[lb];
        #pragma unroll
        for (int q = 0; q < 8; q++) { xp[q] = xq[q]; hp[q] = hq[q]; }

        // LN stats over x (16 elems), packed
        ull s2 = xp[0];
        ull q2 = mul2(xp[0], xp[0]);
        #pragma unroll
        for (int d = 1; d < 8; d++) {
            add2(s2, xp[d]);
            fma2(q2, xp[d], xp[d]);
        }
        float2 su = up(s2), qu = up(q2);
        float mu   = (su.x + su.y) * 0.0625f;
        float var  = fmaf(-mu, mu, (qu.x + qu.y) * 0.0625f);
        float rstd = rsqrtf(var + 1e-5f);

        // gate dots, packed: ax = W'_rows . x_raw, ah = W_hh_rows . h
        ull ax0 = 0, ax1 = 0, ax2 = 0, ax3 = 0;
        ull ah0 = 0, ah1 = 0, ah2 = 0, ah3 = 0;
        #pragma unroll
        for (int d = 0; d < 8; d++) {
            ull xv = xp[d], hv = hp[d];
            fma2(ax0, Wx[d * 4 + 0], xv);
            fma2(ax1, Wx[d * 4 + 1], xv);
            fma2(ax2, Wx[d * 4 + 2], xv);
            fma2(ax3, Wx[d * 4 + 3], xv);
            fma2(ah0, Wh[d * 4 + 0], hv);
            fma2(ah1, Wh[d * 4 + 1], hv);
            fma2(ah2, Wh[d * 4 + 2], hv);
            fma2(ah3, Wh[d * 4 + 3], hv);
        }
        float2 x0 = up(ax0), x1 = up(ax1), x2 = up(ax2), x3 = up(ax3);
        float2 h0 = up(ah0), h1 = up(ah1), h2 = up(ah2), h3 = up(ah3);

        float gi = fmaf(rstd, fmaf(-mu, Sv.x, x0.x + x0.y), Bv.x) + (h0.x + h0.y);
        float gf = fmaf(rstd, fmaf(-mu, Sv.y, x1.x + x1.y), Bv.y) + (h1.x + h1.y);
        float gg = fmaf(rstd, fmaf(-mu, Sv.z, x2.x + x2.y), Bv.z) + (h2.x + h2.y);
        float go = fmaf(rstd, fmaf(-mu, Sv.w, x3.x + x3.y), Bv.w) + (h3.x + h3.y);

        float ig = sigm(gi), fg = sigm(gf), og = sigm(go);
        float gt = tanh_f(gg);
        c = fmaf(fg, c, ig * gt);
        h = og * tanh_f(c);

        __syncwarp();
        hbuf[lb][j] = h;
        __syncwarp();

        // state += h @ W_out.T + b_out  (lanes 0..11), packed
        if (j < SD) {
            ull ao = 0;
            #pragma unroll
            for (int q = 0; q < 8; q++) fma2(ao, Wo[q], hq[q]);
            float2 aou = up(ao);
            st += (aou.x + aou.y) + bo;
        }

        // sincos normalization via intra-half-warp shuffle
        float other = __shfl_sync(0xffffffffu, st, p, 16);
        if ((j >= 1) && (j <= 6)) {
            float nrm = __fsqrt_rn(fmaf(st, st, other * other)) + 1e-8f;
            st = __fdividef(st, nrm);
        }

        if (j < SD) {
            outp[t * SD + j] = st;
            xbuf[lb][j] = st;   // state part of next step's x
        }
    }
}

extern "C" void kernel_launch(void* const* d_in, const int* in_sizes, int n_in,
                              void* d_out, int out_size) {
    const float* init_state = (const float*)d_in[0];
    const float* commands   = (const float*)d_in[1];
    const float* ln_gamma   = (const float*)d_in[2];
    const float* ln_beta    = (const float*)d_in[3];
    const float* W_in       = (const float*)d_in[4];
    const float* b_in       = (const float*)d_in[5];
    const float* W_ih       = (const float*)d_in[6];
    const float* W_hh       = (const float*)d_in[7];
    const float* b_ih       = (const float*)d_in[8];
    const float* b_hh       = (const float*)d_in[9];
    const float* W_out      = (const float*)d_in[10];
    const float* b_out      = (const float*)d_in[11];
    float* out = (float*)d_out;

    vm_prep<<<1, 64>>>(ln_gamma, ln_beta, W_in, b_in, W_ih, W_hh, b_ih, b_hh, W_out, b_out);
    vm_main<<<NBLOCKS, THREADS>>>(init_state, commands, out);
}

// round 9
// speedup vs baseline: 1.2761x; 1.1640x over previous
#include <cuda_runtime.h>

#define B_TOT 8192
#define T_STEPS 256
#define SD 12          // state dim
#define AD 4           // action dim
#define DD 16          // D = SD + AD
#define HH 16          // hidden
#define GG 64          // 4*H

#define WPB 4                      // warps (= batches) per block
#define THREADS (WPB * 32)
#define NBLOCKS (B_TOT / WPB)

typedef unsigned long long ull;

// Per-lane packed weights. lane = hi*16 + j owns gate rows r0 = hi*16+j, r1 = hi*16+j+32.
// g_WxL[lane*16 + s*8 + p] = (Wc'[r_s][2p], Wc'[r_s][2p+1])   (gamma folded into Wc')
__device__ float2 g_WxL[32 * 16];
__device__ float2 g_WhL[32 * 16];
__device__ float4 g_SBL[32];       // (S_r0, S_r1, B_r0, B_r1)
__device__ float2 g_WoL[SD * 8];   // W_out packed pairs, row-major
__device__ float  g_boL[SD];

__global__ void vm_prep(const float* __restrict__ ln_gamma,
                        const float* __restrict__ ln_beta,
                        const float* __restrict__ W_in,   // [H][D]
                        const float* __restrict__ b_in,   // [H]
                        const float* __restrict__ W_ih,   // [G][H]
                        const float* __restrict__ W_hh,   // [G][H]
                        const float* __restrict__ b_ih,
                        const float* __restrict__ b_hh,
                        const float* __restrict__ W_out,  // [SD][H]
                        const float* __restrict__ b_out)
{
    int r = threadIdx.x;   // gate row 0..63
    if (r < GG) {
        int j    = r & 15;
        int hi   = (r >> 4) & 1;
        int s    = r >> 5;
        int lane = hi * 16 + j;
        float wp[DD];
        float S = 0.f, bB = 0.f;
        for (int d = 0; d < DD; d++) {
            float acc = 0.f;
            for (int k = 0; k < HH; k++) acc += W_ih[r * HH + k] * W_in[k * DD + d];
            wp[d] = acc * ln_gamma[d];             // fold gamma
            bB += acc * ln_beta[d];                // fold beta
            S += wp[d];
        }
        float bi = 0.f;
        for (int k = 0; k < HH; k++) bi += W_ih[r * HH + k] * b_in[k];
        ((float*)&g_SBL[lane])[s]     = S;
        ((float*)&g_SBL[lane])[2 + s] = bB + bi + b_ih[r] + b_hh[r];
        for (int p = 0; p < 8; p++) {
            g_WxL[lane * 16 + s * 8 + p] = make_float2(wp[2 * p], wp[2 * p + 1]);
            g_WhL[lane * 16 + s * 8 + p] = make_float2(W_hh[r * HH + 2 * p],
                                                       W_hh[r * HH + 2 * p + 1]);
        }
    }
    if (r < SD) {
        for (int p = 0; p < 8; p++)
            g_WoL[r * 8 + p] = make_float2(W_out[r * HH + 2 * p], W_out[r * HH + 2 * p + 1]);
        g_boL[r] = b_out[r];
    }
}

__device__ __forceinline__ void fma2(ull& acc, ull w, ull x) {
    asm("fma.rn.f32x2 %0, %1, %2, %0;" : "+l"(acc) : "l"(w), "l"(x));
}
__device__ __forceinline__ void add2(ull& acc, ull x) {
    asm("add.rn.f32x2 %0, %0, %1;" : "+l"(acc) : "l"(x));
}
__device__ __forceinline__ ull mul2(ull a, ull b) {
    ull r; asm("mul.rn.f32x2 %0, %1, %2;" : "=l"(r) : "l"(a), "l"(b)); return r;
}
__device__ __forceinline__ float2 up(ull v) {
    float2 r; asm("mov.b64 {%0, %1}, %2;" : "=f"(r.x), "=f"(r.y) : "l"(v)); return r;
}
__device__ __forceinline__ float ex2_(float x) {
    float r; asm("ex2.approx.f32 %0, %1;" : "=f"(r) : "f"(x)); return r;
}
__device__ __forceinline__ float rcp_(float x) {
    float r; asm("rcp.approx.f32 %0, %1;" : "=f"(r) : "f"(x)); return r;
}
// sigmoid(x) = 1/(1+e^-x)   (2 MUFU, 4 instr)
__device__ __forceinline__ float sigm(float x) {
    return rcp_(1.f + ex2_(x * -1.44269504f));
}
// tanh(x) = 1 - 2/(e^{2x}+1)  (2 MUFU, 5 instr, sign-safe at both infinities)
__device__ __forceinline__ float tanh5(float x) {
    return fmaf(-2.f, rcp_(1.f + ex2_(x * 2.88539008f)), 1.f);
}

__global__ __launch_bounds__(THREADS, 3) void vm_main(
    const float* __restrict__ init_state,   // [B][1][SD]
    const float* __restrict__ commands,     // [B][T][AD]
    float* __restrict__ out)                // [B][T][SD]
{
    __shared__ __align__(16) float xbuf[WPB][16];
    __shared__ __align__(16) float hbuf[WPB][16];

    int tid  = threadIdx.x;
    int w    = tid >> 5;     // warp in block = local batch
    int lane = tid & 31;
    int j    = lane & 15;
    int hi   = lane >> 4;    // 0: rows j (i), j+32 (g); 1: rows j+16 (f), j+48 (o)
    int b    = blockIdx.x * WPB + w;

    // loop-invariant weights in registers
    ull Wx[16], Wh[16];
    const ull* wx = (const ull*)g_WxL + lane * 16;
    const ull* wh = (const ull*)g_WhL + lane * 16;
    #pragma unroll
    for (int i = 0; i < 16; i++) { Wx[i] = wx[i]; Wh[i] = wh[i]; }

    int jw = (j < SD) ? j : 0;          // clamped W_out row (all lanes compute, few use)
    ull Wo[8];
    const ull* wo = (const ull*)g_WoL + jw * 8;
    #pragma unroll
    for (int i = 0; i < 8; i++) Wo[i] = wo[i];
    float bo  = g_boL[jw];
    float4 SB = g_SBL[lane];

    bool stlane  = (hi == 0) && (j < SD);
    bool cmdlane = (hi == 1) && (j >= SD);

    float st = 0.f;
    if (stlane) st = init_state[b * SD + j];
    float c = 0.f;
    ull hp[8];
    #pragma unroll
    for (int q = 0; q < 8; q++) hp[q] = 0ULL;

    const float* cmdp = commands + (size_t)b * (T_STEPS * AD);
    float*       outp = out      + (size_t)b * (T_STEPS * SD);

    // x for t=0 + prefetch cmd for t=1
    float cmd_next = 0.f;
    if (stlane)  xbuf[w][j] = st;
    if (cmdlane) xbuf[w][j] = cmdp[j - SD];
    if (cmdlane) cmd_next   = cmdp[AD + (j - SD)];
    __syncwarp();

    const ull* xq = (const ull*)xbuf[w];
    const ull* hq = (const ull*)hbuf[w];
    ull xp[8];
    #pragma unroll
    for (int q = 0; q < 8; q++) xp[q] = xq[q];

    int  p16 = (j >= 1 && j <= 6) ? (j + ((j & 1) ? 1 : -1)) : j;
    bool isc = (j >= 1 && j <= 6);

    for (int t = 0; t < T_STEPS; t++) {
        // LayerNorm stats over raw x (folded affine applied via S/B)
        ull s2 = xp[0], q2 = mul2(xp[0], xp[0]);
        #pragma unroll
        for (int d = 1; d < 8; d++) { add2(s2, xp[d]); fma2(q2, xp[d], xp[d]); }
        float2 su = up(s2), qu = up(q2);
        float mu   = (su.x + su.y) * 0.0625f;
        float var  = fmaf(-mu, mu, (qu.x + qu.y) * 0.0625f);
        float rstd = rsqrtf(var + 1e-5f);

        // gate dots for this lane's two rows (x-part and h-part)
        ull a0x = mul2(Wx[0], xp[0]);
        ull a1x = mul2(Wx[8], xp[0]);
        ull a0h = mul2(Wh[0], hp[0]);
        ull a1h = mul2(Wh[8], hp[0]);
        #pragma unroll
        for (int d = 1; d < 8; d++) {
            fma2(a0x, Wx[d],     xp[d]);
            fma2(a1x, Wx[8 + d], xp[d]);
            fma2(a0h, Wh[d],     hp[d]);
            fma2(a1h, Wh[8 + d], hp[d]);
        }
        float2 u0 = up(a0x), u1 = up(a1x), v0 = up(a0h), v1 = up(a1h);
        float g0 = fmaf(rstd, fmaf(-mu, SB.x, u0.x + u0.y), SB.z) + (v0.x + v0.y);
        float g1 = fmaf(rstd, fmaf(-mu, SB.y, u1.x + u1.y), SB.w) + (v1.x + v1.y);

        // activations: hi=0 lane has (i, g); hi=1 lane has (f, o)
        float sA = sigm(g0);            // sig(i) | sig(f)
        float tB = tanh5(g1);           // tanh(g)      (used by hi=0)
        float sB = sigm(g1);            // sig(o)       (used by hi=1)
        float a  = sA * tB;             // sig(i)*tanh(g) on hi=0
        float send1 = hi ? sA : a;
        float fs = __shfl_xor_sync(0xffffffffu, send1, 16);  // hi=0 receives sig(f)
        float os = __shfl_xor_sync(0xffffffffu, sB, 16);     // hi=0 receives sig(o)
        c = fmaf(fs, c, a);             // valid on hi=0
        float h = os * tanh5(c);

        if (hi == 0) hbuf[w][j] = h;
        __syncwarp();
        #pragma unroll
        for (int q = 0; q < 8; q++) hp[q] = hq[q];

        // state += h @ W_out.T + b_out   (all lanes compute; only stlane uses)
        ull ao = mul2(Wo[0], hp[0]);
        #pragma unroll
        for (int q = 1; q < 8; q++) fma2(ao, Wo[q], hp[q]);
        float2 aou = up(ao);
        st = st + (aou.x + aou.y) + bo;

        // sincos renorm, branch-free
        float other = __shfl_sync(0xffffffffu, st, p16, 16);
        float ss = fmaf(st, st, other * other);
        float rn = rsqrtf(ss);
        st = isc ? st * rn : st;

        if (stlane) outp[t * SD + j] = st;

        // stage x for t+1; prefetch cmd for t+2
        if (stlane)  xbuf[w][j] = st;
        if (cmdlane) xbuf[w][j] = cmd_next;
        int tn = (t + 2 < T_STEPS) ? (t + 2) : (T_STEPS - 1);
        if (cmdlane) cmd_next = cmdp[tn * AD + (j - SD)];
        __syncwarp();
        #pragma unroll
        for (int q = 0; q < 8; q++) xp[q] = xq[q];
    }
}

extern "C" void kernel_launch(void* const* d_in, const int* in_sizes, int n_in,
                              void* d_out, int out_size) {
    const float* init_state = (const float*)d_in[0];
    const float* commands   = (const float*)d_in[1];
    const float* ln_gamma   = (const float*)d_in[2];
    const float* ln_beta    = (const float*)d_in[3];
    const float* W_in       = (const float*)d_in[4];
    const float* b_in       = (const float*)d_in[5];
    const float* W_ih       = (const float*)d_in[6];
    const float* W_hh       = (const float*)d_in[7];
    const float* b_ih       = (const float*)d_in[8];
    const float* b_hh       = (const float*)d_in[9];
    const float* W_out      = (const float*)d_in[10];
    const float* b_out      = (const float*)d_in[11];
    float* out = (float*)d_out;

    vm_prep<<<1, 64>>>(ln_gamma, ln_beta, W_in, b_in, W_ih, W_hh, b_ih, b_hh, W_out, b_out);
    vm_main<<<NBLOCKS, THREADS>>>(init_state, commands, out);
}

// round 10
// speedup vs baseline: 1.3608x; 1.0664x over previous
#include <cuda_runtime.h>

#define B_TOT 8192
#define T_STEPS 256
#define SD 12          // state dim
#define AD 4           // action dim
#define DD 16          // D = SD + AD
#define HH 16          // hidden
#define GG 64          // 4*H

#define WPB 2                      // warps (= batches) per block
#define THREADS (WPB * 32)
#define NBLOCKS (B_TOT / WPB)

typedef unsigned long long ull;

// Per-lane packed weights. lane = hi*16 + j owns gate rows r0 (hi=0: i_j, hi=1: f_j)
// and r1 (hi=0: g_j, hi=1: o_j).
__device__ float2 g_WxL[32 * 16];
__device__ float2 g_WhL[32 * 16];
__device__ float4 g_SBL[32];                    // (S_r0, S_r1, B_r0, B_r1)
__device__ __align__(16) float2 g_WoL[SD * 8];  // W_out packed pairs, row-major
__device__ float  g_boL[SD];

__global__ void vm_prep(const float* __restrict__ ln_gamma,
                        const float* __restrict__ ln_beta,
                        const float* __restrict__ W_in,   // [H][D]
                        const float* __restrict__ b_in,   // [H]
                        const float* __restrict__ W_ih,   // [G][H]
                        const float* __restrict__ W_hh,   // [G][H]
                        const float* __restrict__ b_ih,
                        const float* __restrict__ b_hh,
                        const float* __restrict__ W_out,  // [SD][H]
                        const float* __restrict__ b_out)
{
    int r = threadIdx.x;   // gate row 0..63
    if (r < GG) {
        int j    = r & 15;
        int hi   = (r >> 4) & 1;
        int s    = r >> 5;
        int lane = hi * 16 + j;
        float wp[DD];
        float S = 0.f, bB = 0.f;
        for (int d = 0; d < DD; d++) {
            float acc = 0.f;
            for (int k = 0; k < HH; k++) acc += W_ih[r * HH + k] * W_in[k * DD + d];
            wp[d] = acc * ln_gamma[d];             // fold gamma
            bB += acc * ln_beta[d];                // fold beta
            S += wp[d];
        }
        float bi = 0.f;
        for (int k = 0; k < HH; k++) bi += W_ih[r * HH + k] * b_in[k];
        ((float*)&g_SBL[lane])[s]     = S;
        ((float*)&g_SBL[lane])[2 + s] = bB + bi + b_ih[r] + b_hh[r];
        for (int p = 0; p < 8; p++) {
            g_WxL[lane * 16 + s * 8 + p] = make_float2(wp[2 * p], wp[2 * p + 1]);
            g_WhL[lane * 16 + s * 8 + p] = make_float2(W_hh[r * HH + 2 * p],
                                                       W_hh[r * HH + 2 * p + 1]);
        }
    }
    if (r < SD) {
        for (int p = 0; p < 8; p++)
            g_WoL[r * 8 + p] = make_float2(W_out[r * HH + 2 * p], W_out[r * HH + 2 * p + 1]);
        g_boL[r] = b_out[r];
    }
}

__device__ __forceinline__ void fma2(ull& acc, ull w, ull x) {
    asm("fma.rn.f32x2 %0, %1, %2, %0;" : "+l"(acc) : "l"(w), "l"(x));
}
__device__ __forceinline__ void add2(ull& acc, ull x) {
    asm("add.rn.f32x2 %0, %0, %1;" : "+l"(acc) : "l"(x));
}
__device__ __forceinline__ ull mul2(ull a, ull b) {
    ull r; asm("mul.rn.f32x2 %0, %1, %2;" : "=l"(r) : "l"(a), "l"(b)); return r;
}
__device__ __forceinline__ float2 up(ull v) {
    float2 r; asm("mov.b64 {%0, %1}, %2;" : "=f"(r.x), "=f"(r.y) : "l"(v)); return r;
}
__device__ __forceinline__ float ex2_(float x) {
    float r; asm("ex2.approx.f32 %0, %1;" : "=f"(r) : "f"(x)); return r;
}
__device__ __forceinline__ float rcp_(float x) {
    float r; asm("rcp.approx.f32 %0, %1;" : "=f"(r) : "f"(x)); return r;
}
__device__ __forceinline__ float sigm(float x) {
    return rcp_(1.f + ex2_(x * -1.44269504f));
}
__device__ __forceinline__ float tanh5(float x) {
    return fmaf(-2.f, rcp_(1.f + ex2_(x * 2.88539008f)), 1.f);
}

__global__ __launch_bounds__(THREADS, 8) void vm_main(
    const float* __restrict__ init_state,   // [B][1][SD]
    const float* __restrict__ commands,     // [B][T][AD]
    float* __restrict__ out)                // [B][T][SD]
{
    __shared__ __align__(16) float xbuf[WPB][16];
    __shared__ __align__(16) float hbuf[WPB][16];
    __shared__ ulonglong2 sWo[SD * 5];   // stride 5 quads: <=2-way bank conflict
    __shared__ float sbo[SD];

    int tid  = threadIdx.x;
    int w    = tid >> 5;     // warp in block = local batch
    int lane = tid & 31;
    int j    = lane & 15;
    int hi   = lane >> 4;
    int b    = blockIdx.x * WPB + w;

    // stage W_out into padded smem
    {
        const ulonglong2* gq = (const ulonglong2*)g_WoL;
        for (int i = tid; i < SD * 4; i += THREADS)
            sWo[(i >> 2) * 5 + (i & 3)] = gq[i];
        for (int i = tid; i < SD; i += THREADS) sbo[i] = g_boL[i];
    }

    // loop-invariant gate weights in registers
    ull Wx[16], Wh[16];
    const ull* wx = (const ull*)g_WxL + lane * 16;
    const ull* wh = (const ull*)g_WhL + lane * 16;
    #pragma unroll
    for (int i = 0; i < 16; i++) { Wx[i] = wx[i]; Wh[i] = wh[i]; }
    float4 SB = g_SBL[lane];

    int  jw      = (j < SD) ? j : 0;
    bool stlane  = (hi == 0) && (j < SD);
    bool cmdlane = (hi == 1) && (j >= SD);
    float kk     = hi ? -1.44269504f : 2.88539008f;   // sigm vs tanh exponent scale

    float st = 0.f;
    if (stlane) st = init_state[b * SD + j];
    float c = 0.f;
    ull hp[8];
    #pragma unroll
    for (int q = 0; q < 8; q++) hp[q] = 0ULL;

    const float* cmdp = commands + (size_t)b * (T_STEPS * AD);
    float*       outp = out      + (size_t)b * (T_STEPS * SD);
    int ci = j - SD;   // command component for cmdlane

    // x for t=0 ; prefetch cmds for t=1..4
    if (stlane)  xbuf[w][j] = st;
    if (cmdlane) xbuf[w][j] = cmdp[ci];
    float cb0 = 0.f, cb1 = 0.f, cb2 = 0.f, cb3 = 0.f;
    if (cmdlane) {
        cb0 = cmdp[1 * AD + ci];
        cb1 = cmdp[2 * AD + ci];
        cb2 = cmdp[3 * AD + ci];
        cb3 = cmdp[4 * AD + ci];
    }
    __syncthreads();   // sWo + xbuf visible

    const ulonglong2* xq4 = (const ulonglong2*)xbuf[w];
    const ulonglong2* hq4 = (const ulonglong2*)hbuf[w];
    const ulonglong2* wop = sWo + jw * 5;
    float bo = sbo[jw];

    ull xp[8];
    #pragma unroll
    for (int q = 0; q < 4; q++) {
        ulonglong2 v = xq4[q];
        xp[2 * q] = v.x; xp[2 * q + 1] = v.y;
    }

    int  p16 = (j >= 1 && j <= 6) ? (j + ((j & 1) ? 1 : -1)) : j;
    bool isc = (j >= 1 && j <= 6);

    auto step = [&](int t, float cnext) {
        // LayerNorm stats over raw x (two chains each)
        ull sa = xp[0], sb2 = xp[1];
        ull qa = mul2(xp[0], xp[0]), qb = mul2(xp[1], xp[1]);
        #pragma unroll
        for (int d = 2; d < 8; d += 2) {
            add2(sa, xp[d]);     fma2(qa, xp[d],     xp[d]);
            add2(sb2, xp[d + 1]); fma2(qb, xp[d + 1], xp[d + 1]);
        }
        add2(sa, sb2); add2(qa, qb);
        float2 su = up(sa), qu = up(qa);
        float mu   = (su.x + su.y) * 0.0625f;
        float var  = fmaf(-mu, mu, (qu.x + qu.y) * 0.0625f);
        float rstd = rsqrtf(var + 1e-5f);

        // gate dots for this lane's two rows
        ull a0x = mul2(Wx[0], xp[0]);
        ull a1x = mul2(Wx[8], xp[0]);
        ull a0h = mul2(Wh[0], hp[0]);
        ull a1h = mul2(Wh[8], hp[0]);
        #pragma unroll
        for (int d = 1; d < 8; d++) {
            fma2(a0x, Wx[d],     xp[d]);
            fma2(a1x, Wx[8 + d], xp[d]);
            fma2(a0h, Wh[d],     hp[d]);
            fma2(a1h, Wh[8 + d], hp[d]);
        }
        float2 u0 = up(a0x), u1 = up(a1x), v0 = up(a0h), v1h = up(a1h);
        float g0 = fmaf(rstd, fmaf(-mu, SB.x, u0.x + u0.y), SB.z) + (v0.x + v0.y);
        float g1 = fmaf(rstd, fmaf(-mu, SB.y, u1.x + u1.y), SB.w) + (v1h.x + v1h.y);

        // activations: hi=0 -> (sig i, tanh g) ; hi=1 -> (sig f, sig o)
        float sA = sigm(g0);
        float r1 = rcp_(1.f + ex2_(g1 * kk));
        float v1 = hi ? r1 : fmaf(-2.f, r1, 1.f);
        float a  = sA * v1;                               // sig(i)*tanh(g) on hi=0
        float send1 = hi ? sA : a;
        float fs = __shfl_xor_sync(0xffffffffu, send1, 16);  // hi=0 gets sig(f)
        float os = __shfl_xor_sync(0xffffffffu, v1, 16);     // hi=0 gets sig(o)
        c = fmaf(fs, c, a);
        float h = os * tanh5(c);

        if (hi == 0) hbuf[w][j] = h;
        __syncwarp();
        #pragma unroll
        for (int q = 0; q < 4; q++) {
            ulonglong2 v = hq4[q];
            hp[2 * q] = v.x; hp[2 * q + 1] = v.y;
        }

        // state += h @ W_out.T + b_out  (two accumulator chains)
        ulonglong2 w0 = wop[0], w1 = wop[1], w2 = wop[2], w3 = wop[3];
        ull ao0 = mul2(w0.x, hp[0]);
        ull ao1 = mul2(w2.x, hp[4]);
        fma2(ao0, w0.y, hp[1]); fma2(ao1, w2.y, hp[5]);
        fma2(ao0, w1.x, hp[2]); fma2(ao1, w3.x, hp[6]);
        fma2(ao0, w1.y, hp[3]); fma2(ao1, w3.y, hp[7]);
        add2(ao0, ao1);
        float2 aou = up(ao0);
        st = st + (aou.x + aou.y) + bo;

        // sincos renorm, branch-free
        float other = __shfl_sync(0xffffffffu, st, p16, 16);
        float rn = rsqrtf(fmaf(st, st, other * other));
        st = isc ? st * rn : st;

        if (stlane) { outp[t * SD + j] = st; xbuf[w][j] = st; }
        if (cmdlane) xbuf[w][j] = cnext;
        __syncwarp();
        #pragma unroll
        for (int q = 0; q < 4; q++) {
            ulonglong2 v = xq4[q];
            xp[2 * q] = v.x; xp[2 * q + 1] = v.y;
        }
    };

    for (int tb = 0; tb < T_STEPS; tb += 4) {
        // prefetch commands for steps tb+5 .. tb+8 (clamped)
        float n0 = 0.f, n1 = 0.f, n2 = 0.f, n3 = 0.f;
        if (cmdlane) {
            int i0 = tb + 5; if (i0 > T_STEPS - 1) i0 = T_STEPS - 1;
            int i1 = tb + 6; if (i1 > T_STEPS - 1) i1 = T_STEPS - 1;
            int i2 = tb + 7; if (i2 > T_STEPS - 1) i2 = T_STEPS - 1;
            int i3 = tb + 8; if (i3 > T_STEPS - 1) i3 = T_STEPS - 1;
            n0 = cmdp[i0 * AD + ci];
            n1 = cmdp[i1 * AD + ci];
            n2 = cmdp[i2 * AD + ci];
            n3 = cmdp[i3 * AD + ci];
        }
        step(tb + 0, cb0);
        step(tb + 1, cb1);
        step(tb + 2, cb2);
        step(tb + 3, cb3);
        cb0 = n0; cb1 = n1; cb2 = n2; cb3 = n3;
    }
}

extern "C" void kernel_launch(void* const* d_in, const int* in_sizes, int n_in,
                              void* d_out, int out_size) {
    const float* init_state = (const float*)d_in[0];
    const float* commands   = (const float*)d_in[1];
    const float* ln_gamma   = (const float*)d_in[2];
    const float* ln_beta    = (const float*)d_in[3];
    const float* W_in       = (const float*)d_in[4];
    const float* b_in       = (const float*)d_in[5];
    const float* W_ih       = (const float*)d_in[6];
    const float* W_hh       = (const float*)d_in[7];
    const float* b_ih       = (const float*)d_in[8];
    const float* b_hh       = (const float*)d_in[9];
    const float* W_out      = (const float*)d_in[10];
    const float* b_out      = (const float*)d_in[11];
    float* out = (float*)d_out;

    vm_prep<<<1, 64>>>(ln_gamma, ln_beta, W_in, b_in, W_ih, W_hh, b_ih, b_hh, W_out, b_out);
    vm_main<<<NBLOCKS, THREADS>>>(init_state, commands, out);
}